// round 2
// baseline (speedup 1.0000x reference)
#include <cuda_runtime.h>

// ---------------------------------------------------------------------------
// QuantumBranch: B=524288 elements, NQ=4 qubits, NL=2 layers, PD=64.
// Strategy:
//   setup_kernel (1 block, 64 thr):
//     - warp0 lanes 0..15: build V[16][16] complex = (shared-circuit unitary U)
//       with column phases (-i)^popcount(j) folded in.
//     - warp1: fold LayerNorm into precomputed constants:
//       centered+gamma-folded W (paired for f32x2), bgg, beta, and the
//       variance quadratic form (4x4 M, v, c). Deterministic shfl reductions.
//   qmain (thread-per-element):
//     y = V r  (r = real product-state magnitudes), probs, signed butterflies
//     -> z[4] -> softmax -> epilogue via quadratic-form variance.
//     Output staged through padded shared memory for coalesced STG.128.
// ---------------------------------------------------------------------------

typedef unsigned long long u64;

__device__ float2 g_V[16][16];   // [col j][row i]
__device__ float4 g_epi[32][3];  // per d-pair: A={w0p,w1p}, B={w2p,w3p}, C={bggp,betap}
__device__ float4 g_varM[4];
__device__ float4 g_varv;
__device__ float  g_varc;

__device__ __forceinline__ u64 pk2(float a, float b) {
    u64 r; asm("mov.b64 %0,{%1,%2};" : "=l"(r) : "f"(a), "f"(b)); return r;
}
__device__ __forceinline__ void upk2(u64 v, float& a, float& b) {
    asm("mov.b64 {%0,%1},%2;" : "=f"(a), "=f"(b) : "l"(v));
}
__device__ __forceinline__ u64 f2fma(u64 a, u64 b, u64 c) {
    u64 d; asm("fma.rn.f32x2 %0,%1,%2,%3;" : "=l"(d) : "l"(a), "l"(b), "l"(c)); return d;
}
__device__ __forceinline__ u64 f2mul(u64 a, u64 b) {
    u64 d; asm("mul.rn.f32x2 %0,%1,%2;" : "=l"(d) : "l"(a), "l"(b)); return d;
}

__device__ __forceinline__ float wsum(float v) {
    #pragma unroll
    for (int o = 16; o; o >>= 1) v += __shfl_xor_sync(0xffffffffu, v, o);
    return v;
}

__global__ void setup_kernel(const float* __restrict__ wts,
                             const float* __restrict__ W,
                             const float* __restrict__ b,
                             const float* __restrict__ gm,
                             const float* __restrict__ bt)
{
    int tid = threadIdx.x;

    // ---- warp0 lanes 0..15: build V column j = tid ----
    if (tid < 16) {
        int j = tid;
        float2 st[16];
        #pragma unroll
        for (int k = 0; k < 16; k++) st[k] = make_float2(k == j ? 1.f : 0.f, 0.f);

        #pragma unroll
        for (int l = 0; l < 2; l++) {
            // Rot gates, qubits 0..3
            #pragma unroll
            for (int w = 0; w < 4; w++) {
                const float* g = wts + (l * 4 + w) * 3;
                float phi = g[0], th = g[1], om = g[2];
                float a = 0.5f * (phi + om), bb = 0.5f * (phi - om), hh = 0.5f * th;
                float sa, ca, sb, cb, stt, ct;
                __sincosf(a, &sa, &ca);
                __sincosf(bb, &sb, &cb);
                __sincosf(hh, &stt, &ct);
                // ep = (ca,-sa), em = (cb,-sb)
                float2 g00 = make_float2( ca * ct, -sa * ct);
                float2 g01 = make_float2(-cb * stt, -sb * stt);   // -conj(em)*st
                float2 g10 = make_float2( cb * stt, -sb * stt);   //  em*st
                float2 g11 = make_float2( ca * ct,  sa * ct);     //  conj(ep)*ct
                int mask = 8 >> w;  // qubit w <-> bit (3-w)
                #pragma unroll
                for (int k = 0; k < 16; k++) {
                    if (!(k & mask)) {
                        int k1 = k | mask;
                        float2 A = st[k], Bv = st[k1];
                        float2 t0, t1;
                        t0.x = g00.x * A.x - g00.y * A.y + g01.x * Bv.x - g01.y * Bv.y;
                        t0.y = g00.x * A.y + g00.y * A.x + g01.x * Bv.y + g01.y * Bv.x;
                        t1.x = g10.x * A.x - g10.y * A.y + g11.x * Bv.x - g11.y * Bv.y;
                        t1.y = g10.x * A.y + g10.y * A.x + g11.x * Bv.y + g11.y * Bv.x;
                        st[k] = t0; st[k1] = t1;
                    }
                }
            }
            // CNOT ring, range r
            int r = (l == 0) ? 1 : 2;
            #pragma unroll
            for (int w = 0; w < 4; w++) {
                int cq = w, tq = (w + r) & 3;
                int mc = 8 >> cq, mt = 8 >> tq;
                #pragma unroll
                for (int k = 0; k < 16; k++) {
                    if ((k & mc) && !(k & mt)) {
                        float2 tmp = st[k]; st[k] = st[k | mt]; st[k | mt] = tmp;
                    }
                }
            }
        }
        // fold column phase (-i)^popcount(j)
        int pop = __popc(j) & 3;
        #pragma unroll
        for (int k = 0; k < 16; k++) {
            float2 v = st[k], o;
            if      (pop == 0) o = v;
            else if (pop == 1) o = make_float2( v.y, -v.x);
            else if (pop == 2) o = make_float2(-v.x, -v.y);
            else               o = make_float2(-v.y,  v.x);
            g_V[j][k] = o;
        }
    }

    // ---- warp1 (tid 32..63): LayerNorm fold constants ----
    if (tid >= 32 && tid < 64) {
        int lane = tid - 32;
        const float inv64 = 1.f / 64.f;
        float wa[4], wb[4];
        #pragma unroll
        for (int i = 0; i < 4; i++) { wa[i] = W[lane * 4 + i]; wb[i] = W[(lane + 32) * 4 + i]; }
        float ba = b[lane], bbv = b[lane + 32];

        float cm[4];
        #pragma unroll
        for (int i = 0; i < 4; i++) cm[i] = wsum(wa[i] + wb[i]) * inv64;
        float bm = wsum(ba + bbv) * inv64;
        #pragma unroll
        for (int i = 0; i < 4; i++) { wa[i] -= cm[i]; wb[i] -= cm[i]; }
        ba -= bm; bbv -= bm;

        float M[4][4];
        #pragma unroll
        for (int i = 0; i < 4; i++) {
            #pragma unroll
            for (int k = 0; k < 4; k++) {
                if (k >= i) {
                    float v = wsum(wa[i] * wa[k] + wb[i] * wb[k]) * inv64;
                    M[i][k] = v; M[k][i] = v;
                }
            }
        }
        float vv[4];
        #pragma unroll
        for (int i = 0; i < 4; i++) vv[i] = wsum(wa[i] * ba + wb[i] * bbv) * (2.f * inv64);
        float vc = wsum(ba * ba + bbv * bbv) * inv64;

        if (lane == 0) {
            g_varM[0] = make_float4(M[0][0], M[0][1], M[0][2], M[0][3]);
            g_varM[1] = make_float4(M[1][0], M[1][1], M[1][2], M[1][3]);
            g_varM[2] = make_float4(M[2][0], M[2][1], M[2][2], M[2][3]);
            g_varM[3] = make_float4(M[3][0], M[3][1], M[3][2], M[3][3]);
            g_varv    = make_float4(vv[0], vv[1], vv[2], vv[3]);
            g_varc    = vc;
        }

        float ga = gm[lane], gb = gm[lane + 32];
        float bea = bt[lane], beb = bt[lane + 32];
        float* e = (float*)g_epi;
        {
            int d = lane, p = d >> 1, par = d & 1;
            float* ep = e + p * 12;
            ep[0 + par] = wa[0] * ga; ep[2 + par] = wa[1] * ga;
            ep[4 + par] = wa[2] * ga; ep[6 + par] = wa[3] * ga;
            ep[8 + par] = ba * ga;    ep[10 + par] = bea;
        }
        {
            int d = lane + 32, p = d >> 1, par = d & 1;
            float* ep = e + p * 12;
            ep[0 + par] = wb[0] * gb; ep[2 + par] = wb[1] * gb;
            ep[4 + par] = wb[2] * gb; ep[6 + par] = wb[3] * gb;
            ep[8 + par] = bbv * gb;   ep[10 + par] = beb;
        }
    }
}

__global__ __launch_bounds__(128) void qmain(const float4* __restrict__ x4,
                                             ulonglong2* __restrict__ out16)
{
    __shared__ ulonglong2 sV[16][8];       // col-major: [j][i2] = rows 2*i2, 2*i2+1
    __shared__ ulonglong2 sEpi[32][3];
    __shared__ float4 sVarM[4];
    __shared__ float4 sVarv;
    __shared__ float  sVarc;
    __shared__ ulonglong2 stg[4][32][17];  // padded staging: conflict-free

    int tid = threadIdx.x;
    ((float4*)sV)[tid] = ((const float4*)g_V)[tid];            // 128 x 16B
    if (tid < 96) ((float4*)sEpi)[tid] = ((const float4*)g_epi)[tid];
    if (tid < 4)  sVarM[tid] = g_varM[tid];
    if (tid == 4) sVarv = g_varv;
    if (tid == 5) sVarc = g_varc;
    __syncthreads();

    int idx = blockIdx.x * 128 + tid;
    float4 xv = x4[idx];

    // tanh via exp (accurate), half-angle sincos. half = tanh(x)*pi/2 in (-pi/2, pi/2)
    float cc[4], ss[4];
    {
        float xs[4] = {xv.x, xv.y, xv.z, xv.w};
        #pragma unroll
        for (int w = 0; w < 4; w++) {
            float e  = __expf(2.f * xs[w]);
            float th = __fdividef(e - 1.f, e + 1.f);
            __sincosf(th * 1.5707963267948966f, &ss[w], &cc[w]);
        }
    }
    // product-state magnitudes r_k = P[k>>2] * Q[k&3]
    float Pp[4] = {cc[0]*cc[1], cc[0]*ss[1], ss[0]*cc[1], ss[0]*ss[1]};
    float Qq[4] = {cc[2]*cc[3], cc[2]*ss[3], ss[2]*cc[3], ss[2]*ss[3]};

    // y = V r  (complex16 x real16), packed f32x2 FMAs
    u64 y[16];
    #pragma unroll
    for (int j = 0; j < 16; j++) {
        float rj = Pp[j >> 2] * Qq[j & 3];
        u64 rr = pk2(rj, rj);
        #pragma unroll
        for (int i2 = 0; i2 < 8; i2++) {
            ulonglong2 v = sV[j][i2];
            if (j == 0) {
                y[2*i2]   = f2mul(v.x, rr);
                y[2*i2+1] = f2mul(v.y, rr);
            } else {
                y[2*i2]   = f2fma(v.x, rr, y[2*i2]);
                y[2*i2+1] = f2fma(v.y, rr, y[2*i2+1]);
            }
        }
    }

    float p[16];
    #pragma unroll
    for (int k = 0; k < 16; k++) {
        float a, bv; upk2(y[k], a, bv);
        p[k] = fmaf(a, a, bv * bv);
    }

    // signed butterfly sums: qubit w <-> bit (3-w)
    float s0a[8]; float z3 = 0.f;
    #pragma unroll
    for (int jj = 0; jj < 8; jj++) { s0a[jj] = p[2*jj] + p[2*jj+1]; z3 += p[2*jj] - p[2*jj+1]; }
    float s1a[4]; float z2 = 0.f;
    #pragma unroll
    for (int jj = 0; jj < 4; jj++) { s1a[jj] = s0a[2*jj] + s0a[2*jj+1]; z2 += s0a[2*jj] - s0a[2*jj+1]; }
    float z1 = (s1a[0] - s1a[1]) + (s1a[2] - s1a[3]);
    float z0 = (s1a[0] + s1a[1]) - (s1a[2] + s1a[3]);

    // softmax (z in [-1,1], no max-shift needed)
    float e0 = __expf(z0), e1 = __expf(z1), e2 = __expf(z2), e3 = __expf(z3);
    float rs = __fdividef(1.f, e0 + e1 + e2 + e3);
    float q0 = e0 * rs, q1 = e1 * rs, q2 = e2 * rs, q3 = e3 * rs;

    // variance as quadratic form
    float4 M0 = sVarM[0], M1 = sVarM[1], M2 = sVarM[2], M3 = sVarM[3];
    float4 vvv = sVarv;
    float t0 = vvv.x + M0.x*q0 + M0.y*q1 + M0.z*q2 + M0.w*q3;
    float t1 = vvv.y + M1.x*q0 + M1.y*q1 + M1.z*q2 + M1.w*q3;
    float t2 = vvv.z + M2.x*q0 + M2.y*q1 + M2.z*q2 + M2.w*q3;
    float t3 = vvv.w + M3.x*q0 + M3.y*q1 + M3.z*q2 + M3.w*q3;
    float var = sVarc + q0*t0 + q1*t1 + q2*t2 + q3*t3;
    float inv = rsqrtf(var + 1e-5f);

    u64 qq0 = pk2(q0, q0), qq1 = pk2(q1, q1), qq2 = pk2(q2, q2), qq3 = pk2(q3, q3);
    u64 ii  = pk2(inv, inv);

    int w = tid >> 5, lane = tid & 31;
    #pragma unroll
    for (int t = 0; t < 16; t++) {
        ulonglong2 A0 = sEpi[2*t][0],   B0 = sEpi[2*t][1],   C0 = sEpi[2*t][2];
        u64 h0 = f2fma(A0.x, qq0, C0.x);
        h0 = f2fma(A0.y, qq1, h0);
        h0 = f2fma(B0.x, qq2, h0);
        h0 = f2fma(B0.y, qq3, h0);
        u64 o0 = f2fma(h0, ii, C0.y);
        ulonglong2 A1 = sEpi[2*t+1][0], B1 = sEpi[2*t+1][1], C1 = sEpi[2*t+1][2];
        u64 h1 = f2fma(A1.x, qq0, C1.x);
        h1 = f2fma(A1.y, qq1, h1);
        h1 = f2fma(B1.x, qq2, h1);
        h1 = f2fma(B1.y, qq3, h1);
        u64 o1 = f2fma(h1, ii, C1.y);
        stg[w][lane][t] = make_ulonglong2(o0, o1);
    }
    __syncwarp();

    // coalesced writeout: 512B per STG.128 burst per warp
    size_t base = ((size_t)blockIdx.x * 128 + (size_t)w * 32) * 16;
    #pragma unroll
    for (int t = 0; t < 16; t++) {
        int f4 = t * 32 + lane;
        out16[base + f4] = stg[w][f4 >> 4][f4 & 15];
    }
}

extern "C" void kernel_launch(void* const* d_in, const int* in_sizes, int n_in,
                              void* d_out, int out_size)
{
    const float* x   = (const float*)d_in[0];
    const float* wts = (const float*)d_in[1];
    const float* W   = (const float*)d_in[2];
    const float* b   = (const float*)d_in[3];
    const float* gm  = (const float*)d_in[4];
    const float* bt  = (const float*)d_in[5];
    int B = in_sizes[0] / 4;

    setup_kernel<<<1, 64>>>(wts, W, b, gm, bt);
    qmain<<<B / 128, 128>>>((const float4*)x, (ulonglong2*)d_out);
}